// round 14
// baseline (speedup 1.0000x reference)
#include <cuda_runtime.h>
#include <cuda_bf16.h>
#include <cstdint>

// Problem: feature_matrix (64, 1, 1000, 128) fp32 -> out (64, 1, 1000, 128, 8) fp32
#define NB        64
#define PER_B     128000                 // elements per batch
#define PER_B4    32000                  // input float4 per batch
#define TSTEPS    8
#define RBLK      5                      // reduce blocks per batch
#define RB_F4     6400                   // float4 per reduce block = 5 iters * 5 * 256
#define EBLOCKS_PER_B 125                // encode blocks per batch (2048 out-float4 each)
#define NGROUPS   4
#define GB        (NB / NGROUPS)         // 16 batches per group

// ---------------------------------------------------------------------------
// Device scratch: per-(batch, block) partial min/max + per-batch cut values.
// Plain stores, no init kernel, no atomics, deterministic across replays.
// ---------------------------------------------------------------------------
__device__ float  g_part_min[NB * RBLK];
__device__ float  g_part_max[NB * RBLK];
__device__ float4 g_cuts4[NB * 2];       // [b][parity]: cuts for out positions 0-3 / 4-7

__device__ __forceinline__ unsigned f2ord(float f) {
    unsigned u = __float_as_uint(f);
    return (u & 0x80000000u) ? ~u : (u | 0x80000000u);
}
__device__ __forceinline__ float ord2f(unsigned u) {
    u = (u & 0x80000000u) ? (u & 0x7FFFFFFFu) : ~u;
    return __uint_as_float(u);
}

// grid: (RBLK, GB), block: 256. Each block: 6400 float4 (100KB) in 5 loop
// iterations of 5 front-batched independent LDG.128 per thread. (Proven body.)
__global__ void __launch_bounds__(256) minmax_kernel(const float4* __restrict__ in,
                                                     int b0) {
    const int b = b0 + blockIdx.y;
    const float4* base = in + (size_t)b * PER_B4 + (size_t)blockIdx.x * RB_F4
                            + threadIdx.x;

    float mn =  3.402823466e+38f;
    float mx = -3.402823466e+38f;
    #pragma unroll
    for (int it = 0; it < 5; it++) {
        float4 v0 = base[it * 1280 +    0];
        float4 v1 = base[it * 1280 +  256];
        float4 v2 = base[it * 1280 +  512];
        float4 v3 = base[it * 1280 +  768];
        float4 v4 = base[it * 1280 + 1024];

        float a0 = fminf(fminf(v0.x, v0.y), fminf(v0.z, v0.w));
        float b0v = fmaxf(fmaxf(v0.x, v0.y), fmaxf(v0.z, v0.w));
        float a1 = fminf(fminf(v1.x, v1.y), fminf(v1.z, v1.w));
        float b1 = fmaxf(fmaxf(v1.x, v1.y), fmaxf(v1.z, v1.w));
        float a2 = fminf(fminf(v2.x, v2.y), fminf(v2.z, v2.w));
        float b2 = fmaxf(fmaxf(v2.x, v2.y), fmaxf(v2.z, v2.w));
        float a3 = fminf(fminf(v3.x, v3.y), fminf(v3.z, v3.w));
        float b3 = fmaxf(fmaxf(v3.x, v3.y), fmaxf(v3.z, v3.w));
        float a4 = fminf(fminf(v4.x, v4.y), fminf(v4.z, v4.w));
        float b4 = fmaxf(fmaxf(v4.x, v4.y), fmaxf(v4.z, v4.w));

        mn = fminf(mn, fminf(fminf(fminf(a0, a1), fminf(a2, a3)), a4));
        mx = fmaxf(mx, fmaxf(fmaxf(fmaxf(b0v, b1), fmaxf(b2, b3)), b4));
    }

    #pragma unroll
    for (int off = 16; off > 0; off >>= 1) {
        mn = fminf(mn, __shfl_xor_sync(0xFFFFFFFFu, mn, off));
        mx = fmaxf(mx, __shfl_xor_sync(0xFFFFFFFFu, mx, off));
    }
    __shared__ float smn[8], smx[8];
    const int wid = threadIdx.x >> 5, lid = threadIdx.x & 31;
    if (lid == 0) { smn[wid] = mn; smx[wid] = mx; }
    __syncthreads();
    if (threadIdx.x == 0) {
        mn = smn[0]; mx = smx[0];
        #pragma unroll
        for (int w = 1; w < 8; w++) { mn = fminf(mn, smn[w]); mx = fmaxf(mx, smx[w]); }
        g_part_min[b * RBLK + blockIdx.x] = mn;
        g_part_max[b * RBLK + blockIdx.x] = mx;
    }
}

struct Thresh { float t[TSTEPS]; };

// 1 block, 128 threads = 16 batches x 8 output positions (per group).
// X = max{x in [mn,mx] : RN(RN(8*RN(x-mn))/range) <= t}, binary search over
// ordered-float bits with the reference's exact IEEE-RN formula; monotone RN
// stages make (norm > t) <=> (x > X) bit-identical on [mn, mx].
__global__ void __launch_bounds__(128) cuts_kernel(Thresh th, int b0) {
    const int b = b0 + (threadIdx.x >> 3);
    const int j = threadIdx.x & 7;

    float mn =  3.402823466e+38f;
    float mx = -3.402823466e+38f;
    #pragma unroll
    for (int i = 0; i < RBLK; i++) {
        mn = fminf(mn, g_part_min[b * RBLK + i]);
        mx = fmaxf(mx, g_part_max[b * RBLK + i]);
    }
    const float range = __fsub_rn(mx, mn);
    const float t = th.t[j];

    unsigned lo = f2ord(mn), hi = f2ord(mx);   // invariant: f(lo) <= t (f(mn)=0)
    while (lo < hi) {
        unsigned mid = lo + ((hi - lo + 1u) >> 1);
        float x = ord2f(mid);
        float norm = __fdiv_rn(__fmul_rn(8.0f, __fsub_rn(x, mn)), range);
        if (norm <= t) lo = mid; else hi = mid - 1u;
    }
    reinterpret_cast<float*>(g_cuts4)[b * 8 + j] = ord2f(lo);
}

// One thread -> 8 output float4 slots (warp-contiguous 512B stores, full
// sectors). Slot s = element (s>>1), time-half (s&1). (Proven body.)
// grid: GB*125 = 2000 blocks x 256 per group.
__global__ void __launch_bounds__(256) encode_kernel(const float* __restrict__ in,
                                                     float4* __restrict__ out,
                                                     int b0) {
    const int tid  = threadIdx.x;
    const int gblk = b0 * EBLOCKS_PER_B + blockIdx.x;   // global tile index
    const int b    = b0 + blockIdx.x / EBLOCKS_PER_B;
    const float4 cut = g_cuts4[b * 2 + (tid & 1)];

    const int base_s = gblk * 2048 + tid;
    #pragma unroll
    for (int k = 0; k < 8; k++) {
        const int s = base_s + k * 256;
        const float x = __ldg(in + (s >> 1));
        float4 o;
        o.x = (x > cut.x) ? 1.0f : 0.0f;
        o.y = (x > cut.y) ? 1.0f : 0.0f;
        o.z = (x > cut.z) ? 1.0f : 0.0f;
        o.w = (x > cut.w) ? 1.0f : 0.0f;
        __stcs(out + s, o);              // evict-first: don't flush input from L2
    }
}

// ---------------------------------------------------------------------------
// Streams/events for intra-graph pipelining. Created once at static init
// (outside the harness mem-checkpoint window; not device-memory allocations).
// Every kernel_launch call issues the identical launch DAG with them.
// ---------------------------------------------------------------------------
struct PipeRes {
    cudaStream_t aux[NGROUPS - 1];
    cudaEvent_t  emm[NGROUPS];           // minmax(group g) complete
    cudaEvent_t  ejoin[NGROUPS - 1];     // aux chain complete
    PipeRes() {
        for (int i = 0; i < NGROUPS - 1; i++)
            cudaStreamCreateWithFlags(&aux[i], cudaStreamNonBlocking);
        for (int i = 0; i < NGROUPS; i++)
            cudaEventCreateWithFlags(&emm[i], cudaEventDisableTiming);
        for (int i = 0; i < NGROUPS - 1; i++)
            cudaEventCreateWithFlags(&ejoin[i], cudaEventDisableTiming);
    }
};
static PipeRes g_pipe;

// ---------------------------------------------------------------------------
// Host: Threefry-2x32, jax.random.permutation(key(1), 8) with
// jax_threefry_partitionable=True semantics (verified rel_err=0, R2-R13):
//   split (foldlike): subkey = threefry(key, (0, 1))
//   random_bits 32-bit: bits_i = out0 ^ out1 of threefry(subkey, (0, i))
// ---------------------------------------------------------------------------
static inline uint32_t rotl32(uint32_t x, int d) { return (x << d) | (x >> (32 - d)); }

static void threefry2x32(uint32_t k0, uint32_t k1, uint32_t x0, uint32_t x1,
                         uint32_t* o0, uint32_t* o1) {
    const int rotA[4] = {13, 15, 26, 6};
    const int rotB[4] = {17, 29, 16, 24};
    uint32_t ks0 = k0, ks1 = k1, ks2 = k0 ^ k1 ^ 0x1BD11BDAu;
    x0 += ks0; x1 += ks1;
    for (int i = 0; i < 4; i++) { x0 += x1; x1 = rotl32(x1, rotA[i]); x1 ^= x0; }
    x0 += ks1; x1 += ks2 + 1u;
    for (int i = 0; i < 4; i++) { x0 += x1; x1 = rotl32(x1, rotB[i]); x1 ^= x0; }
    x0 += ks2; x1 += ks0 + 2u;
    for (int i = 0; i < 4; i++) { x0 += x1; x1 = rotl32(x1, rotA[i]); x1 ^= x0; }
    x0 += ks0; x1 += ks1 + 3u;
    for (int i = 0; i < 4; i++) { x0 += x1; x1 = rotl32(x1, rotB[i]); x1 ^= x0; }
    x0 += ks1; x1 += ks2 + 4u;
    for (int i = 0; i < 4; i++) { x0 += x1; x1 = rotl32(x1, rotA[i]); x1 ^= x0; }
    x0 += ks2; x1 += ks0 + 5u;
    *o0 = x0; *o1 = x1;
}

extern "C" void kernel_launch(void* const* d_in, const int* in_sizes, int n_in,
                              void* d_out, int out_size) {
    uint32_t sk0, sk1;
    threefry2x32(0u, 1u, 0u, 1u, &sk0, &sk1);
    uint32_t keys[8];
    for (int i = 0; i < 8; i++) {
        uint32_t o0, o1;
        threefry2x32(sk0, sk1, 0u, (uint32_t)i, &o0, &o1);
        keys[i] = o0 ^ o1;
    }
    int perm[8] = {0, 1, 2, 3, 4, 5, 6, 7};
    for (int i = 1; i < 8; i++) {           // stable insertion sort (ascending)
        uint32_t kv = keys[perm[i]];
        int p = perm[i], j = i - 1;
        while (j >= 0 && keys[perm[j]] > kv) { perm[j + 1] = perm[j]; j--; }
        perm[j + 1] = p;
    }
    Thresh th;
    for (int i = 0; i < 8; i++) th.t[i] = (float)perm[i];

    const float*  in_f = (const float*)d_in[0];
    const float4* in4  = (const float4*)in_f;
    float4*       out4 = (float4*)d_out;

    const dim3 mmgrid(RBLK, GB);

    // Group 0 on the main (capture-origin) stream.
    minmax_kernel<<<mmgrid, 256>>>(in4, 0);
    cudaEventRecord(g_pipe.emm[0], 0);
    cuts_kernel<<<1, 128>>>(th, 0);
    encode_kernel<<<GB * EBLOCKS_PER_B, 256>>>(in_f, out4, 0);

    // Groups 1..3 on aux streams: mm(g) ordered after mm(g-1) so it overlaps
    // enc(g-1); each group's own cuts/encode follow in-stream.
    for (int g = 1; g < NGROUPS; g++) {
        cudaStream_t s = g_pipe.aux[g - 1];
        cudaStreamWaitEvent(s, g_pipe.emm[g - 1], 0);     // fork/stagger
        minmax_kernel<<<mmgrid, 256, 0, s>>>(in4, g * GB);
        cudaEventRecord(g_pipe.emm[g], s);
        cuts_kernel<<<1, 128, 0, s>>>(th, g * GB);
        encode_kernel<<<GB * EBLOCKS_PER_B, 256, 0, s>>>(in_f, out4, g * GB);
        cudaEventRecord(g_pipe.ejoin[g - 1], s);
    }
    // Join all aux branches back into the main stream.
    for (int g = 0; g < NGROUPS - 1; g++)
        cudaStreamWaitEvent(0, g_pipe.ejoin[g], 0);
}

// round 15
// speedup vs baseline: 1.1345x; 1.1345x over previous
#include <cuda_runtime.h>
#include <cuda_bf16.h>
#include <cstdint>

// Problem: feature_matrix (64, 1, 1000, 128) fp32 -> out (64, 1, 1000, 128, 8) fp32
#define NB        64
#define PER_B     128000                 // elements per batch
#define PER_B4    32000                  // input float4 per batch
#define TSTEPS    8
#define RBLK      5                      // reduce blocks per batch
#define RB_F4     6400                   // float4 per reduce block = 5 iters * 5 * 256
#define EBLOCKS_PER_B 125                // encode blocks per batch (2048 out-float4 each)

// ---------------------------------------------------------------------------
// Device scratch: per-(batch, block) partial min/max + per-batch cut values.
// Plain stores, no init kernel, no atomics, deterministic across replays.
// ---------------------------------------------------------------------------
__device__ float  g_part_min[NB * RBLK];
__device__ float  g_part_max[NB * RBLK];
__device__ float4 g_cuts4[NB * 2];       // [b][parity]: cuts for out positions 0-3 / 4-7

__device__ __forceinline__ unsigned f2ord(float f) {
    unsigned u = __float_as_uint(f);
    return (u & 0x80000000u) ? ~u : (u | 0x80000000u);
}
__device__ __forceinline__ float ord2f(unsigned u) {
    u = (u & 0x80000000u) ? (u & 0x7FFFFFFFu) : ~u;
    return __uint_as_float(u);
}

// grid: (RBLK, NB), block: 256. Each block: 6400 float4 (100KB) in 5 loop
// iterations of 5 front-batched independent LDG.128 per thread.
__global__ void __launch_bounds__(256) minmax_kernel(const float4* __restrict__ in) {
    const int b = blockIdx.y;
    const float4* base = in + (size_t)b * PER_B4 + (size_t)blockIdx.x * RB_F4
                            + threadIdx.x;

    float mn =  3.402823466e+38f;
    float mx = -3.402823466e+38f;
    #pragma unroll
    for (int it = 0; it < 5; it++) {
        // 5 independent loads, front-batched (no dependent ops between them)
        float4 v0 = base[it * 1280 +    0];
        float4 v1 = base[it * 1280 +  256];
        float4 v2 = base[it * 1280 +  512];
        float4 v3 = base[it * 1280 +  768];
        float4 v4 = base[it * 1280 + 1024];

        float a0 = fminf(fminf(v0.x, v0.y), fminf(v0.z, v0.w));
        float b0 = fmaxf(fmaxf(v0.x, v0.y), fmaxf(v0.z, v0.w));
        float a1 = fminf(fminf(v1.x, v1.y), fminf(v1.z, v1.w));
        float b1 = fmaxf(fmaxf(v1.x, v1.y), fmaxf(v1.z, v1.w));
        float a2 = fminf(fminf(v2.x, v2.y), fminf(v2.z, v2.w));
        float b2 = fmaxf(fmaxf(v2.x, v2.y), fmaxf(v2.z, v2.w));
        float a3 = fminf(fminf(v3.x, v3.y), fminf(v3.z, v3.w));
        float b3 = fmaxf(fmaxf(v3.x, v3.y), fmaxf(v3.z, v3.w));
        float a4 = fminf(fminf(v4.x, v4.y), fminf(v4.z, v4.w));
        float b4 = fmaxf(fmaxf(v4.x, v4.y), fmaxf(v4.z, v4.w));

        mn = fminf(mn, fminf(fminf(fminf(a0, a1), fminf(a2, a3)), a4));
        mx = fmaxf(mx, fmaxf(fmaxf(fmaxf(b0, b1), fmaxf(b2, b3)), b4));
    }

    #pragma unroll
    for (int off = 16; off > 0; off >>= 1) {
        mn = fminf(mn, __shfl_xor_sync(0xFFFFFFFFu, mn, off));
        mx = fmaxf(mx, __shfl_xor_sync(0xFFFFFFFFu, mx, off));
    }
    __shared__ float smn[8], smx[8];
    const int wid = threadIdx.x >> 5, lid = threadIdx.x & 31;
    if (lid == 0) { smn[wid] = mn; smx[wid] = mx; }
    __syncthreads();
    if (threadIdx.x == 0) {
        mn = smn[0]; mx = smx[0];
        #pragma unroll
        for (int w = 1; w < 8; w++) { mn = fminf(mn, smn[w]); mx = fmaxf(mx, smx[w]); }
        g_part_min[b * RBLK + blockIdx.x] = mn;
        g_part_max[b * RBLK + blockIdx.x] = mx;
    }
}

struct Thresh { float t[TSTEPS]; };

// 1 block, 512 threads = 64 batches x 8 output positions.
// X = max{x in [mn,mx] : RN(RN(8*RN(x-mn))/range) <= t}, binary search over
// ordered-float bits with the reference's exact IEEE-RN formula; monotone RN
// stages make (norm > t) <=> (x > X) bit-identical on [mn, mx].
__global__ void __launch_bounds__(512) cuts_kernel(Thresh th) {
    const int b = threadIdx.x >> 3;      // 0..63
    const int j = threadIdx.x & 7;       // output time position 0..7

    float mn =  3.402823466e+38f;
    float mx = -3.402823466e+38f;
    #pragma unroll
    for (int i = 0; i < RBLK; i++) {
        mn = fminf(mn, g_part_min[b * RBLK + i]);
        mx = fmaxf(mx, g_part_max[b * RBLK + i]);
    }
    const float range = __fsub_rn(mx, mn);
    const float t = th.t[j];

    unsigned lo = f2ord(mn), hi = f2ord(mx);   // invariant: f(lo) <= t (f(mn)=0)
    while (lo < hi) {
        unsigned mid = lo + ((hi - lo + 1u) >> 1);
        float x = ord2f(mid);
        float norm = __fdiv_rn(__fmul_rn(8.0f, __fsub_rn(x, mn)), range);
        if (norm <= t) lo = mid; else hi = mid - 1u;
    }
    reinterpret_cast<float*>(g_cuts4)[b * 8 + j] = ord2f(lo);
}

// One thread -> 8 output float4 slots (warp-contiguous 512B stores, full
// sectors). Slot s = element (s>>1), time-half (s&1). Streaming stores keep
// the 32MB input L2-resident (loaded by minmax) so encode reads hit L2.
// grid: 8000 blocks x 256 threads; block covers 2048 slots = 1024 elements.
__global__ void __launch_bounds__(256) encode_kernel(const float* __restrict__ in,
                                                     float4* __restrict__ out) {
    const int tid = threadIdx.x;
    const int b   = blockIdx.x / EBLOCKS_PER_B;
    const float4 cut = g_cuts4[b * 2 + (tid & 1)];

    const int base_s = blockIdx.x * 2048 + tid;
    #pragma unroll
    for (int k = 0; k < 8; k++) {
        const int s = base_s + k * 256;
        const float x = __ldg(in + (s >> 1));
        float4 o;
        o.x = (x > cut.x) ? 1.0f : 0.0f;
        o.y = (x > cut.y) ? 1.0f : 0.0f;
        o.z = (x > cut.z) ? 1.0f : 0.0f;
        o.w = (x > cut.w) ? 1.0f : 0.0f;
        __stcs(out + s, o);              // evict-first: don't flush input from L2
    }
}

// ---------------------------------------------------------------------------
// Host: Threefry-2x32, jax.random.permutation(key(1), 8) with
// jax_threefry_partitionable=True semantics (verified rel_err=0, R2-R14):
//   split (foldlike): subkey = threefry(key, (0, 1))
//   random_bits 32-bit: bits_i = out0 ^ out1 of threefry(subkey, (0, i))
// ---------------------------------------------------------------------------
static inline uint32_t rotl32(uint32_t x, int d) { return (x << d) | (x >> (32 - d)); }

static void threefry2x32(uint32_t k0, uint32_t k1, uint32_t x0, uint32_t x1,
                         uint32_t* o0, uint32_t* o1) {
    const int rotA[4] = {13, 15, 26, 6};
    const int rotB[4] = {17, 29, 16, 24};
    uint32_t ks0 = k0, ks1 = k1, ks2 = k0 ^ k1 ^ 0x1BD11BDAu;
    x0 += ks0; x1 += ks1;
    for (int i = 0; i < 4; i++) { x0 += x1; x1 = rotl32(x1, rotA[i]); x1 ^= x0; }
    x0 += ks1; x1 += ks2 + 1u;
    for (int i = 0; i < 4; i++) { x0 += x1; x1 = rotl32(x1, rotB[i]); x1 ^= x0; }
    x0 += ks2; x1 += ks0 + 2u;
    for (int i = 0; i < 4; i++) { x0 += x1; x1 = rotl32(x1, rotA[i]); x1 ^= x0; }
    x0 += ks0; x1 += ks1 + 3u;
    for (int i = 0; i < 4; i++) { x0 += x1; x1 = rotl32(x1, rotB[i]); x1 ^= x0; }
    x0 += ks1; x1 += ks2 + 4u;
    for (int i = 0; i < 4; i++) { x0 += x1; x1 = rotl32(x1, rotA[i]); x1 ^= x0; }
    x0 += ks2; x1 += ks0 + 5u;
    *o0 = x0; *o1 = x1;
}

extern "C" void kernel_launch(void* const* d_in, const int* in_sizes, int n_in,
                              void* d_out, int out_size) {
    uint32_t sk0, sk1;
    threefry2x32(0u, 1u, 0u, 1u, &sk0, &sk1);
    uint32_t keys[8];
    for (int i = 0; i < 8; i++) {
        uint32_t o0, o1;
        threefry2x32(sk0, sk1, 0u, (uint32_t)i, &o0, &o1);
        keys[i] = o0 ^ o1;
    }
    int perm[8] = {0, 1, 2, 3, 4, 5, 6, 7};
    for (int i = 1; i < 8; i++) {           // stable insertion sort (ascending)
        uint32_t kv = keys[perm[i]];
        int p = perm[i], j = i - 1;
        while (j >= 0 && keys[perm[j]] > kv) { perm[j + 1] = perm[j]; j--; }
        perm[j + 1] = p;
    }
    Thresh th;
    for (int i = 0; i < 8; i++) th.t[i] = (float)perm[i];

    const float* in_f = (const float*)d_in[0];

    dim3 rgrid(RBLK, NB);
    minmax_kernel<<<rgrid, 256>>>((const float4*)in_f);
    cuts_kernel<<<1, 512>>>(th);
    encode_kernel<<<NB * EBLOCKS_PER_B, 256>>>(in_f, (float4*)d_out);
}